// round 15
// baseline (speedup 1.0000x reference)
#include <cuda_runtime.h>
#include <cstdint>
#include <math.h>

#define CC   256
#define K3   768
#define HWL  3136
#define WD   56
#define HALF_PI 1.5707963f
#define INV56   (1.0f / 56.0f)
#define RS768   0.03608439182435161f   // 1/sqrt(768)
#define NSPLIT  3

// Scratch (device globals — no allocations allowed).
__device__ uint32_t g_w3f [2 * 96 * 8 * 32 * 4];          // tf32(W3), A-frag
__device__ uint32_t g_t1tf[16 * K3 * HWL + 128];          // tf32(unfold(x)) row-major
__device__ float    g_t3  [16 * CC * HWL];                // fp32 t3
__device__ uint32_t g_t6f [16 * 96 * 392 * 32 * 2 + 1024];// tf32(max(t3,sin)), B-frag
__device__ float    g_t7p [16 * NSPLIT * K3 * CC];        // split-K partials
__device__ uint32_t g_t7f [16 * 2 * 96 * 8 * 32 * 4];     // tf32(t7), A-frag

// Host-side stream/event objects (host resources only, created at load).
static cudaStream_t g_s2;
static cudaEvent_t  g_e1, g_e2, g_e6a, g_e3;
namespace {
struct StreamInit {
    StreamInit() {
        cudaStreamCreateWithFlags(&g_s2, cudaStreamNonBlocking);
        cudaEventCreateWithFlags(&g_e1,  cudaEventDisableTiming);
        cudaEventCreateWithFlags(&g_e2,  cudaEventDisableTiming);
        cudaEventCreateWithFlags(&g_e6a, cudaEventDisableTiming);
        cudaEventCreateWithFlags(&g_e3,  cudaEventDisableTiming);
    }
} g_stream_init;
}

static __device__ __forceinline__ uint32_t f2tf(float f) {
    uint32_t u; asm("cvt.rna.tf32.f32 %0, %1;" : "=r"(u) : "f"(f)); return u;
}
static __device__ __forceinline__ uint32_t cvta_s(const void* p) {
    uint32_t a;
    asm("{ .reg .u64 t; cvta.to.shared.u64 t, %1; cvt.u32.u64 %0, t; }" : "=r"(a) : "l"(p));
    return a;
}
static __device__ __forceinline__ void mma8(float d[4], const uint32_t* a, const uint32_t* b) {
    asm volatile(
        "mma.sync.aligned.m16n8k8.row.col.f32.tf32.tf32.f32 "
        "{%0,%1,%2,%3},{%4,%5,%6,%7},{%8,%9},{%0,%1,%2,%3};"
        : "+f"(d[0]), "+f"(d[1]), "+f"(d[2]), "+f"(d[3])
        : "r"(a[0]), "r"(a[1]), "r"(a[2]), "r"(a[3]), "r"(b[0]), "r"(b[1]));
}
#define CPA(dst, src) asm volatile("cp.async.cg.shared.global [%0], [%1], 16;" :: "r"(dst), "l"(src) : "memory")
#define CPC()         asm volatile("cp.async.commit_group;" ::: "memory")
#define CPW(N)        asm volatile("cp.async.wait_group %0;" :: "n"(N) : "memory")

// =====================================================================
// Precompute kernels
// =====================================================================
__global__ __launch_bounds__(256) void p_cvtw(const float* __restrict__ w) {
    int id = blockIdx.x * 256 + threadIdx.x;
    int l = id & 31, g = l >> 2, c4 = l & 3;
    int mt = (id >> 5) & 7;
    int r = id >> 8;
    int kt = r % 96, mb = r / 96;
    int m = mb * 128 + mt * 16 + g;
    int k = kt * 8 + c4;
    uint4 o;
    o.x = f2tf(w[(size_t)m * K3 + k]);
    o.y = f2tf(w[(size_t)(m + 8) * K3 + k]);
    o.z = f2tf(w[(size_t)m * K3 + k + 4]);
    o.w = f2tf(w[(size_t)(m + 8) * K3 + k + 4]);
    reinterpret_cast<uint4*>(g_w3f)[id] = o;
}
__global__ __launch_bounds__(256) void p_t1(const float* __restrict__ x) {
    int idx = blockIdx.x * 256 + threadIdx.x;
    int p4 = idx % (HWL / 4);
    int r  = idx / (HWL / 4);
    int k  = r % K3, n = r / K3;
    int c = k / 3, tap = k - 3 * c, sh = 2 * tap - 2;
    int p = p4 * 4, w = p % WD;
    const float* xr = x + ((size_t)n * CC + c) * HWL + p + sh;
    float v[4];
#pragma unroll
    for (int j = 0; j < 4; j++)
        v[j] = ((unsigned)(w + j + sh) < WD) ? xr[j] : 0.f;
    reinterpret_cast<uint4*>(g_t1tf)[idx] =
        make_uint4(f2tf(v[0]), f2tf(v[1]), f2tf(v[2]), f2tf(v[3]));
}
// t6 -> B-frag pairs via smem staging; n0 = batch offset
__global__ __launch_bounds__(256) void p_t6(const float* __restrict__ x, int n0) {
    __shared__ float S[8 * 72];
    const int t = threadIdx.x;
    int bid = blockIdx.x;
    int ptg = bid % 49; bid /= 49;
    int kq  = bid % 96; int n = n0 + bid / 96;
    const int p0 = ptg * 64;
#pragma unroll
    for (int q = 0; q < 2; q++) {
        int item = t + q * 256;
        int k8 = item >> 6, pi = item & 63;
        int k = kq * 8 + k8;
        int c = k / 3, tap = k - 3 * c, sh = 2 * tap - 2;
        int p = p0 + pi, w = p % WD;
        const float* base = x + ((size_t)n * CC + c) * HWL + p;
        float s = ((unsigned)(w + sh) < WD) ? __sinf(HALF_PI * base[sh]) : 0.f;
        float v = fmaxf(g_t3[((size_t)n * CC + c) * HWL + p], s);
        S[k8 * 72 + pi] = v;
    }
    __syncthreads();
    int ptl = t >> 5, l = t & 31;
    int g = l >> 2, c4 = l & 3;
    int pl = ptl * 8 + g;
    uint2 o;
    o.x = f2tf(S[c4 * 72 + pl]);
    o.y = f2tf(S[(c4 + 4) * 72 + pl]);
    reinterpret_cast<uint2*>(g_t6f)[(((size_t)n * 96 + kq) * 392 + ptg * 8 + ptl) * 32 + l] = o;
}
// reduce split-K partials, * INV56 * p7w -> t7 in A-frag chunks
__global__ __launch_bounds__(256) void k2r(const float* __restrict__ p7w) {
    int id = blockIdx.x * 256 + threadIdx.x;
    int l = id & 31, g = l >> 2, c4 = l & 3;
    int mt = (id >> 5) & 7;
    int r = id >> 8;
    int kt = r % 96; r /= 96;
    int mb = r & 1;  int n = r >> 1;
    const float* P = g_t7p + (size_t)n * NSPLIT * (K3 * CC);
    uint32_t vals[4];
#pragma unroll
    for (int q = 0; q < 4; q++) {
        int dk = (q >> 1) * 4, dm = (q & 1) * 8;
        int k = kt * 8 + c4 + dk;
        int m = mb * 128 + mt * 16 + g + dm;
        int off = k * CC + m;
        float sum = P[off] + P[K3 * CC + off] + P[2 * K3 * CC + off];
        vals[q] = f2tf(sum * INV56 * p7w[off]);
    }
    reinterpret_cast<uint4*>(g_t7f)[id] = make_uint4(vals[0], vals[1], vals[2], vals[3]);
}

#define ACC_INIT float acc[4][4][4]; \
    _Pragma("unroll") for (int i0 = 0; i0 < 4; i0++) \
    _Pragma("unroll") for (int j0 = 0; j0 < 4; j0++) \
    _Pragma("unroll") for (int r0 = 0; r0 < 4; r0++) acc[i0][j0][r0] = 0.f;

// ---------------- Stage 1: t3 = W3 @ t1 ----------------
__global__ __launch_bounds__(256, 2) void k1() {
    __shared__ uint32_t As[3 * 2048];
    __shared__ uint32_t Bs[3 * 2176];
    const int t = threadIdx.x, lane = t & 31, warp = t >> 5;
    const int n = blockIdx.z, mb = blockIdx.y, m0 = mb * 128, p0 = blockIdx.x * 128;
    const int g = lane >> 2, c4 = lane & 3;
    const int wm = (warp & 1) * 64, wn = (warp >> 1) * 32;
    const uint32_t* t1n = g_t1tf + (size_t)n * K3 * HWL;

    const uint32_t* srcA = g_w3f + ((size_t)mb * 96 * 256 + t) * 4;
    const int rB0 = t >> 5, sB0 = t & 31;
    const uint32_t* srcB0 = t1n + (size_t)rB0 * HWL + p0 + sB0 * 4;
    const uint32_t* srcB1 = t1n + (size_t)(rB0 + 8) * HWL + p0 + sB0 * 4;
    const uint32_t dA  = cvta_s(As) + t * 16;
    const uint32_t dB0 = cvta_s(&Bs[rB0 * 136 + sB0 * 4]);
    const uint32_t dB1 = cvta_s(&Bs[(rB0 + 8) * 136 + sB0 * 4]);

    auto load = [&](int kb, int buf) {
        int k0 = kb * 16;
        CPA(dA + buf * 8192,        srcA + kb * 2048);
        CPA(dA + buf * 8192 + 4096, srcA + kb * 2048 + 1024);
        CPA(dB0 + buf * 8704, srcB0 + (size_t)k0 * HWL);
        CPA(dB1 + buf * 8704, srcB1 + (size_t)k0 * HWL);
    };

    ACC_INIT
    load(0, 0); CPC(); load(1, 1); CPC();
    const int NK = 48;
    for (int kb = 0; kb < NK; kb++) {
        int b = kb % 3;
        CPW(1); __syncthreads();
        if (kb + 2 < NK) load(kb + 2, (kb + 2) % 3);
        CPC();
        const uint32_t* Ab = As + b * 2048;
        const uint32_t* Bb = Bs + b * 2176;
#pragma unroll
        for (int th = 0; th < 2; th++) {
            int kc = th * 8 + c4;
            uint4 af[4]; uint32_t bf[4][2];
#pragma unroll
            for (int mt = 0; mt < 4; mt++)
                af[mt] = *reinterpret_cast<const uint4*>(
                    Ab + ((th * 8 + (warp & 1) * 4 + mt) * 32 + lane) * 4);
#pragma unroll
            for (int nt = 0; nt < 4; nt++) {
                const uint32_t* bp = Bb + kc * 136 + wn + nt * 8 + g;
                bf[nt][0] = bp[0]; bf[nt][1] = bp[544];
            }
#pragma unroll
            for (int mt = 0; mt < 4; mt++)
#pragma unroll
                for (int nt = 0; nt < 4; nt++)
                    mma8(acc[mt][nt], reinterpret_cast<const uint32_t*>(&af[mt]), bf[nt]);
        }
    }
    float* t3n = g_t3 + (size_t)n * CC * HWL;
#pragma unroll
    for (int mt = 0; mt < 4; mt++)
#pragma unroll
        for (int nt = 0; nt < 4; nt++) {
            int row = m0 + wm + mt * 16 + g;
            int col = p0 + wn + nt * 8 + c4 * 2;
            if (col < HWL) {
                *reinterpret_cast<float2*>(&t3n[(size_t)row * HWL + col]) =
                    make_float2(acc[mt][nt][0], acc[mt][nt][1]);
                *reinterpret_cast<float2*>(&t3n[(size_t)(row + 8) * HWL + col]) =
                    make_float2(acc[mt][nt][2], acc[mt][nt][3]);
            }
        }
}

// ---------------- Stage 2: t7p = t2 @ x^T (split-K=3) ----------------
__global__ __launch_bounds__(256, 2) void k2() {
    __shared__ uint32_t As[3 * 2560];
    __shared__ uint32_t Bs[3 * 2560];
    const int t = threadIdx.x, lane = t & 31, warp = t >> 5;
    const int zz = blockIdx.z, n = zz / NSPLIT, s = zz - n * NSPLIT;
    const int m0 = blockIdx.y * 128, c0 = blockIdx.x * 128;
    const int pbase = s * 1056;
    const int NK = (s == 2) ? 64 : 66;
    const int g = lane >> 2, c4 = lane & 3;
    const int wm = (warp & 1) * 64, wn = (warp >> 1) * 32;
    const uint32_t* t1n = g_t1tf + (size_t)n * K3 * HWL;

    const int rA = t >> 2, sA = t & 3;
    int mk0 = m0 + rA, mk1 = m0 + rA + 64;
    int sk0 = (mk0 >= 3) ? mk0 - 3 : mk0 + 765;
    int sk1 = (mk1 >= 3) ? mk1 - 3 : mk1 + 765;
    const uint32_t* srcA0 = t1n + (size_t)sk0 * HWL + pbase + sA * 4;
    const uint32_t* srcA1 = t1n + (size_t)sk1 * HWL + pbase + sA * 4;
    const uint32_t* srcB0 = t1n + (size_t)(3 * (c0 + rA) + 1) * HWL + pbase + sA * 4;
    const uint32_t* srcB1 = t1n + (size_t)(3 * (c0 + rA + 64) + 1) * HWL + pbase + sA * 4;
    const uint32_t dA0 = cvta_s(&As[rA * 20 + sA * 4]);
    const uint32_t dA1 = cvta_s(&As[(rA + 64) * 20 + sA * 4]);
    const uint32_t dB0 = cvta_s(&Bs[rA * 20 + sA * 4]);
    const uint32_t dB1 = cvta_s(&Bs[(rA + 64) * 20 + sA * 4]);

    auto load = [&](int kb, int buf) {
        int o = kb * 16;
        CPA(dA0 + buf * 10240, srcA0 + o);
        CPA(dA1 + buf * 10240, srcA1 + o);
        CPA(dB0 + buf * 10240, srcB0 + o);
        CPA(dB1 + buf * 10240, srcB1 + o);
    };

    ACC_INIT
    load(0, 0); CPC(); load(1, 1); CPC();
    for (int kb = 0; kb < NK; kb++) {
        int b = kb % 3;
        CPW(1); __syncthreads();
        if (kb + 2 < NK) load(kb + 2, (kb + 2) % 3);
        CPC();
        const uint32_t* Ab = As + b * 2560;
        const uint32_t* Bb = Bs + b * 2560;
#pragma unroll
        for (int th = 0; th < 2; th++) {
            int kc = th * 8 + c4;
            uint32_t af[4][4], bf[4][2];
#pragma unroll
            for (int mt = 0; mt < 4; mt++) {
                const uint32_t* ap = Ab + (wm + mt * 16 + g) * 20 + kc;
                af[mt][0] = ap[0]; af[mt][1] = ap[160]; af[mt][2] = ap[4]; af[mt][3] = ap[164];
            }
#pragma unroll
            for (int nt = 0; nt < 4; nt++) {
                const uint32_t* bp = Bb + (wn + nt * 8 + g) * 20 + kc;
                bf[nt][0] = bp[0]; bf[nt][1] = bp[4];
            }
#pragma unroll
            for (int mt = 0; mt < 4; mt++)
#pragma unroll
                for (int nt = 0; nt < 4; nt++) mma8(acc[mt][nt], af[mt], bf[nt]);
        }
    }
    float* dst = g_t7p + (size_t)(n * NSPLIT + s) * K3 * CC;
#pragma unroll
    for (int mt = 0; mt < 4; mt++)
#pragma unroll
        for (int nt = 0; nt < 4; nt++) {
            int row = m0 + wm + mt * 16 + g;
            int col = c0 + wn + nt * 8 + c4 * 2;
            *reinterpret_cast<float2*>(&dst[(size_t)row * CC + col]) =
                make_float2(acc[mt][nt][0], acc[mt][nt][1]);
            *reinterpret_cast<float2*>(&dst[(size_t)(row + 8) * CC + col]) =
                make_float2(acc[mt][nt][2], acc[mt][nt][3]);
        }
}

// ---------------- Stage 3: out = (t6^T @ t7) / sqrt(768); n0 = batch offset ----------------
__global__ __launch_bounds__(256, 2) void k3(float* __restrict__ out, int n0) {
    __shared__ uint32_t As[3 * 2048];
    __shared__ uint32_t Bs[3 * 2048];
    const int t = threadIdx.x, lane = t & 31, warp = t >> 5;
    const int n = n0 + blockIdx.z, mb = blockIdx.y, m0 = mb * 128;
    const int p0 = blockIdx.x * 128, pt0 = blockIdx.x * 16;
    const int g = lane >> 2, c4 = lane & 3;
    const int wm = (warp & 1) * 64, wn = (warp >> 1) * 32;

    const uint32_t* srcA = g_t7f + ((size_t)n * 49152 + (size_t)mb * 96 * 256 + t) * 4;
    const uint32_t* srcB = g_t6f + (((size_t)n * 96 * 392 + pt0) * 32) * 2 + t * 4;
    const uint32_t dA = cvta_s(As) + t * 16;
    const uint32_t dB = cvta_s(Bs) + t * 16;

    auto load = [&](int kb, int buf) {
        CPA(dA + buf * 8192,        srcA + kb * 2048);
        CPA(dA + buf * 8192 + 4096, srcA + kb * 2048 + 1024);
        CPA(dB + buf * 8192,        srcB + (size_t)kb * 50176);
        CPA(dB + buf * 8192 + 4096, srcB + (size_t)kb * 50176 + 25088);
    };

    ACC_INIT
    load(0, 0); CPC(); load(1, 1); CPC();
    const int NK = 48;
    for (int kb = 0; kb < NK; kb++) {
        int b = kb % 3;
        CPW(1); __syncthreads();
        if (kb + 2 < NK) load(kb + 2, (kb + 2) % 3);
        CPC();
        const uint32_t* Ab = As + b * 2048;
        const uint32_t* Bb = Bs + b * 2048;
#pragma unroll
        for (int th = 0; th < 2; th++) {
            uint4 af[4]; uint2 bf[4];
#pragma unroll
            for (int mt = 0; mt < 4; mt++)
                af[mt] = *reinterpret_cast<const uint4*>(
                    Ab + ((th * 8 + (warp & 1) * 4 + mt) * 32 + lane) * 4);
#pragma unroll
            for (int nt = 0; nt < 4; nt++)
                bf[nt] = *reinterpret_cast<const uint2*>(
                    Bb + ((th * 16 + (warp >> 1) * 4 + nt) * 32 + lane) * 2);
#pragma unroll
            for (int mt = 0; mt < 4; mt++)
#pragma unroll
                for (int nt = 0; nt < 4; nt++)
                    mma8(acc[mt][nt], reinterpret_cast<const uint32_t*>(&af[mt]),
                                      reinterpret_cast<const uint32_t*>(&bf[nt]));
        }
    }
#pragma unroll
    for (int mt = 0; mt < 4; mt++)
#pragma unroll
        for (int nt = 0; nt < 4; nt++) {
            int row = m0 + wm + mt * 16 + g;
            int col = p0 + wn + nt * 8 + c4 * 2;
            if (col < HWL) {
                float* o0 = out + ((size_t)n * CC + row) * HWL + col;
                float* o1 = out + ((size_t)n * CC + row + 8) * HWL + col;
                *reinterpret_cast<float2*>(o0) =
                    make_float2(acc[mt][nt][0] * RS768, acc[mt][nt][1] * RS768);
                *reinterpret_cast<float2*>(o1) =
                    make_float2(acc[mt][nt][2] * RS768, acc[mt][nt][3] * RS768);
            }
        }
}

extern "C" void kernel_launch(void* const* d_in, const int* in_sizes, int n_in,
                              void* d_out, int out_size) {
    const float* x   = (const float*)d_in[0];   // (16, 256, 56, 56)
    const float* W3  = (const float*)d_in[1];   // (256, 768)
    const float* p7w = (const float*)d_in[2];   // (1, 256, 3, 256)
    float* out = (float*)d_out;                 // (16, 256, 56, 56)

    // null: p_cvtw -> p_t1 -> [e1] -> k1 -> p_t6_a -> [e6a] -> p_t6_b
    //       -> (wait e2) -> k3_b -> (wait e3)
    // s2:   (wait e1) -> k2 -> k2r -> [e2] -> (wait e6a) -> k3_a -> [e3]
    p_cvtw<<<192, 256>>>(W3);
    p_t1  <<<37632, 256>>>(x);
    cudaEventRecord(g_e1, 0);

    cudaStreamWaitEvent(g_s2, g_e1, 0);
    k2    <<<dim3(2, 6, 48), 256, 0, g_s2>>>();
    k2r   <<<3072, 256, 0, g_s2>>>(p7w);
    cudaEventRecord(g_e2, g_s2);

    k1    <<<dim3(25, 2, 16), 256>>>();
    p_t6  <<<37632, 256>>>(x, 0);
    cudaEventRecord(g_e6a, 0);
    p_t6  <<<37632, 256>>>(x, 8);

    cudaStreamWaitEvent(g_s2, g_e6a, 0);
    k3    <<<dim3(25, 2, 8), 256, 0, g_s2>>>(out, 0);
    cudaEventRecord(g_e3, g_s2);

    cudaStreamWaitEvent(0, g_e2, 0);
    k3    <<<dim3(25, 2, 8), 256>>>(out, 8);
    cudaStreamWaitEvent(0, g_e3, 0);     // join
}

// round 16
// speedup vs baseline: 1.0185x; 1.0185x over previous
#include <cuda_runtime.h>
#include <cstdint>
#include <math.h>

#define CC   256
#define K3   768
#define HWL  3136
#define WD   56
#define HALF_PI 1.5707963f
#define INV56   (1.0f / 56.0f)
#define RS768   0.03608439182435161f   // 1/sqrt(768)
#define NSPLIT  3

// Scratch (device globals — no allocations allowed).
__device__ uint32_t g_w3f [2 * 96 * 8 * 32 * 4];          // tf32(W3), A-frag
__device__ uint32_t g_t1tf[16 * K3 * HWL + 128];          // tf32(unfold(x)) row-major
__device__ float    g_t3  [16 * CC * HWL];                // fp32 t3
__device__ uint32_t g_t6f [16 * 96 * 392 * 32 * 2 + 1024];// tf32(max(t3,sin)), B-frag
__device__ float    g_t7p [16 * NSPLIT * K3 * CC];        // split-K partials
__device__ uint32_t g_t7f [16 * 2 * 96 * 8 * 32 * 4];     // tf32(t7), A-frag

// Host-side stream/event objects (host resources only, created at load).
static cudaStream_t g_s2;
static cudaEvent_t  g_e1a, g_e1b, g_e2;
namespace {
struct StreamInit {
    StreamInit() {
        cudaStreamCreateWithFlags(&g_s2, cudaStreamNonBlocking);
        cudaEventCreateWithFlags(&g_e1a, cudaEventDisableTiming);
        cudaEventCreateWithFlags(&g_e1b, cudaEventDisableTiming);
        cudaEventCreateWithFlags(&g_e2,  cudaEventDisableTiming);
    }
} g_stream_init;
}

static __device__ __forceinline__ uint32_t f2tf(float f) {
    uint32_t u; asm("cvt.rna.tf32.f32 %0, %1;" : "=r"(u) : "f"(f)); return u;
}
static __device__ __forceinline__ uint32_t cvta_s(const void* p) {
    uint32_t a;
    asm("{ .reg .u64 t; cvta.to.shared.u64 t, %1; cvt.u32.u64 %0, t; }" : "=r"(a) : "l"(p));
    return a;
}
static __device__ __forceinline__ void mma8(float d[4], const uint32_t* a, const uint32_t* b) {
    asm volatile(
        "mma.sync.aligned.m16n8k8.row.col.f32.tf32.tf32.f32 "
        "{%0,%1,%2,%3},{%4,%5,%6,%7},{%8,%9},{%0,%1,%2,%3};"
        : "+f"(d[0]), "+f"(d[1]), "+f"(d[2]), "+f"(d[3])
        : "r"(a[0]), "r"(a[1]), "r"(a[2]), "r"(a[3]), "r"(b[0]), "r"(b[1]));
}
#define CPA(dst, src) asm volatile("cp.async.cg.shared.global [%0], [%1], 16;" :: "r"(dst), "l"(src) : "memory")
#define CPC()         asm volatile("cp.async.commit_group;" ::: "memory")
#define CPW(N)        asm volatile("cp.async.wait_group %0;" :: "n"(N) : "memory")

// =====================================================================
// Precompute kernels
// =====================================================================
__global__ __launch_bounds__(256) void p_cvtw(const float* __restrict__ w) {
    int id = blockIdx.x * 256 + threadIdx.x;
    int l = id & 31, g = l >> 2, c4 = l & 3;
    int mt = (id >> 5) & 7;
    int r = id >> 8;
    int kt = r % 96, mb = r / 96;
    int m = mb * 128 + mt * 16 + g;
    int k = kt * 8 + c4;
    uint4 o;
    o.x = f2tf(w[(size_t)m * K3 + k]);
    o.y = f2tf(w[(size_t)(m + 8) * K3 + k]);
    o.z = f2tf(w[(size_t)m * K3 + k + 4]);
    o.w = f2tf(w[(size_t)(m + 8) * K3 + k + 4]);
    reinterpret_cast<uint4*>(g_w3f)[id] = o;
}
// t1 row-major; n0 = batch offset (covers 8 batches per launch)
__global__ __launch_bounds__(256) void p_t1(const float* __restrict__ x, int n0) {
    int idx = blockIdx.x * 256 + threadIdx.x;
    int p4 = idx % (HWL / 4);
    int r  = idx / (HWL / 4);
    int k  = r % K3;
    int n  = n0 + r / K3;
    int c = k / 3, tap = k - 3 * c, sh = 2 * tap - 2;
    int p = p4 * 4, w = p % WD;
    const float* xr = x + ((size_t)n * CC + c) * HWL + p + sh;
    float v[4];
#pragma unroll
    for (int j = 0; j < 4; j++)
        v[j] = ((unsigned)(w + j + sh) < WD) ? xr[j] : 0.f;
    reinterpret_cast<uint4*>(g_t1tf)[(size_t)n * (K3 * HWL / 4) + (size_t)(r % K3) * (HWL / 4) + p4] =
        make_uint4(f2tf(v[0]), f2tf(v[1]), f2tf(v[2]), f2tf(v[3]));
}
// t6 -> B-frag pairs via smem staging
__global__ __launch_bounds__(256) void p_t6(const float* __restrict__ x) {
    __shared__ float S[8 * 72];
    const int t = threadIdx.x;
    int bid = blockIdx.x;
    int ptg = bid % 49; bid /= 49;
    int kq  = bid % 96; int n = bid / 96;
    const int p0 = ptg * 64;
#pragma unroll
    for (int q = 0; q < 2; q++) {
        int item = t + q * 256;
        int k8 = item >> 6, pi = item & 63;
        int k = kq * 8 + k8;
        int c = k / 3, tap = k - 3 * c, sh = 2 * tap - 2;
        int p = p0 + pi, w = p % WD;
        const float* base = x + ((size_t)n * CC + c) * HWL + p;
        float s = ((unsigned)(w + sh) < WD) ? __sinf(HALF_PI * base[sh]) : 0.f;
        float v = fmaxf(g_t3[((size_t)n * CC + c) * HWL + p], s);
        S[k8 * 72 + pi] = v;
    }
    __syncthreads();
    int ptl = t >> 5, l = t & 31;
    int g = l >> 2, c4 = l & 3;
    int pl = ptl * 8 + g;
    uint2 o;
    o.x = f2tf(S[c4 * 72 + pl]);
    o.y = f2tf(S[(c4 + 4) * 72 + pl]);
    reinterpret_cast<uint2*>(g_t6f)[(((size_t)n * 96 + kq) * 392 + ptg * 8 + ptl) * 32 + l] = o;
}
// reduce split-K partials, * INV56 * p7w -> t7 in A-frag chunks
__global__ __launch_bounds__(256) void k2r(const float* __restrict__ p7w) {
    int id = blockIdx.x * 256 + threadIdx.x;
    int l = id & 31, g = l >> 2, c4 = l & 3;
    int mt = (id >> 5) & 7;
    int r = id >> 8;
    int kt = r % 96; r /= 96;
    int mb = r & 1;  int n = r >> 1;
    const float* P = g_t7p + (size_t)n * NSPLIT * (K3 * CC);
    uint32_t vals[4];
#pragma unroll
    for (int q = 0; q < 4; q++) {
        int dk = (q >> 1) * 4, dm = (q & 1) * 8;
        int k = kt * 8 + c4 + dk;
        int m = mb * 128 + mt * 16 + g + dm;
        int off = k * CC + m;
        float sum = P[off] + P[K3 * CC + off] + P[2 * K3 * CC + off];
        vals[q] = f2tf(sum * INV56 * p7w[off]);
    }
    reinterpret_cast<uint4*>(g_t7f)[id] = make_uint4(vals[0], vals[1], vals[2], vals[3]);
}

#define ACC_INIT float acc[4][4][4]; \
    _Pragma("unroll") for (int i0 = 0; i0 < 4; i0++) \
    _Pragma("unroll") for (int j0 = 0; j0 < 4; j0++) \
    _Pragma("unroll") for (int r0 = 0; r0 < 4; r0++) acc[i0][j0][r0] = 0.f;

// ---------------- Stage 1: t3 = W3 @ t1 ----------------
__global__ __launch_bounds__(256, 2) void k1() {
    __shared__ uint32_t As[3 * 2048];
    __shared__ uint32_t Bs[3 * 2176];
    const int t = threadIdx.x, lane = t & 31, warp = t >> 5;
    const int n = blockIdx.z, mb = blockIdx.y, m0 = mb * 128, p0 = blockIdx.x * 128;
    const int g = lane >> 2, c4 = lane & 3;
    const int wm = (warp & 1) * 64, wn = (warp >> 1) * 32;
    const uint32_t* t1n = g_t1tf + (size_t)n * K3 * HWL;

    const uint32_t* srcA = g_w3f + ((size_t)mb * 96 * 256 + t) * 4;
    const int rB0 = t >> 5, sB0 = t & 31;
    const uint32_t* srcB0 = t1n + (size_t)rB0 * HWL + p0 + sB0 * 4;
    const uint32_t* srcB1 = t1n + (size_t)(rB0 + 8) * HWL + p0 + sB0 * 4;
    const uint32_t dA  = cvta_s(As) + t * 16;
    const uint32_t dB0 = cvta_s(&Bs[rB0 * 136 + sB0 * 4]);
    const uint32_t dB1 = cvta_s(&Bs[(rB0 + 8) * 136 + sB0 * 4]);

    auto load = [&](int kb, int buf) {
        int k0 = kb * 16;
        CPA(dA + buf * 8192,        srcA + kb * 2048);
        CPA(dA + buf * 8192 + 4096, srcA + kb * 2048 + 1024);
        CPA(dB0 + buf * 8704, srcB0 + (size_t)k0 * HWL);
        CPA(dB1 + buf * 8704, srcB1 + (size_t)k0 * HWL);
    };

    ACC_INIT
    load(0, 0); CPC(); load(1, 1); CPC();
    const int NK = 48;
    for (int kb = 0; kb < NK; kb++) {
        int b = kb % 3;
        CPW(1); __syncthreads();
        if (kb + 2 < NK) load(kb + 2, (kb + 2) % 3);
        CPC();
        const uint32_t* Ab = As + b * 2048;
        const uint32_t* Bb = Bs + b * 2176;
#pragma unroll
        for (int th = 0; th < 2; th++) {
            int kc = th * 8 + c4;
            uint4 af[4]; uint32_t bf[4][2];
#pragma unroll
            for (int mt = 0; mt < 4; mt++)
                af[mt] = *reinterpret_cast<const uint4*>(
                    Ab + ((th * 8 + (warp & 1) * 4 + mt) * 32 + lane) * 4);
#pragma unroll
            for (int nt = 0; nt < 4; nt++) {
                const uint32_t* bp = Bb + kc * 136 + wn + nt * 8 + g;
                bf[nt][0] = bp[0]; bf[nt][1] = bp[544];
            }
#pragma unroll
            for (int mt = 0; mt < 4; mt++)
#pragma unroll
                for (int nt = 0; nt < 4; nt++)
                    mma8(acc[mt][nt], reinterpret_cast<const uint32_t*>(&af[mt]), bf[nt]);
        }
    }
    float* t3n = g_t3 + (size_t)n * CC * HWL;
#pragma unroll
    for (int mt = 0; mt < 4; mt++)
#pragma unroll
        for (int nt = 0; nt < 4; nt++) {
            int row = m0 + wm + mt * 16 + g;
            int col = p0 + wn + nt * 8 + c4 * 2;
            if (col < HWL) {
                *reinterpret_cast<float2*>(&t3n[(size_t)row * HWL + col]) =
                    make_float2(acc[mt][nt][0], acc[mt][nt][1]);
                *reinterpret_cast<float2*>(&t3n[(size_t)(row + 8) * HWL + col]) =
                    make_float2(acc[mt][nt][2], acc[mt][nt][3]);
            }
        }
}

// ---------------- Stage 2: t7p = t2 @ x^T (split-K=3); n0 = batch offset ----------------
__global__ __launch_bounds__(256, 2) void k2(int n0) {
    __shared__ uint32_t As[3 * 2560];
    __shared__ uint32_t Bs[3 * 2560];
    const int t = threadIdx.x, lane = t & 31, warp = t >> 5;
    const int zz = blockIdx.z, n = n0 + zz / NSPLIT, s = zz % NSPLIT;
    const int m0 = blockIdx.y * 128, c0 = blockIdx.x * 128;
    const int pbase = s * 1056;
    const int NK = (s == 2) ? 64 : 66;
    const int g = lane >> 2, c4 = lane & 3;
    const int wm = (warp & 1) * 64, wn = (warp >> 1) * 32;
    const uint32_t* t1n = g_t1tf + (size_t)n * K3 * HWL;

    const int rA = t >> 2, sA = t & 3;
    int mk0 = m0 + rA, mk1 = m0 + rA + 64;
    int sk0 = (mk0 >= 3) ? mk0 - 3 : mk0 + 765;
    int sk1 = (mk1 >= 3) ? mk1 - 3 : mk1 + 765;
    const uint32_t* srcA0 = t1n + (size_t)sk0 * HWL + pbase + sA * 4;
    const uint32_t* srcA1 = t1n + (size_t)sk1 * HWL + pbase + sA * 4;
    const uint32_t* srcB0 = t1n + (size_t)(3 * (c0 + rA) + 1) * HWL + pbase + sA * 4;
    const uint32_t* srcB1 = t1n + (size_t)(3 * (c0 + rA + 64) + 1) * HWL + pbase + sA * 4;
    const uint32_t dA0 = cvta_s(&As[rA * 20 + sA * 4]);
    const uint32_t dA1 = cvta_s(&As[(rA + 64) * 20 + sA * 4]);
    const uint32_t dB0 = cvta_s(&Bs[rA * 20 + sA * 4]);
    const uint32_t dB1 = cvta_s(&Bs[(rA + 64) * 20 + sA * 4]);

    auto load = [&](int kb, int buf) {
        int o = kb * 16;
        CPA(dA0 + buf * 10240, srcA0 + o);
        CPA(dA1 + buf * 10240, srcA1 + o);
        CPA(dB0 + buf * 10240, srcB0 + o);
        CPA(dB1 + buf * 10240, srcB1 + o);
    };

    ACC_INIT
    load(0, 0); CPC(); load(1, 1); CPC();
    for (int kb = 0; kb < NK; kb++) {
        int b = kb % 3;
        CPW(1); __syncthreads();
        if (kb + 2 < NK) load(kb + 2, (kb + 2) % 3);
        CPC();
        const uint32_t* Ab = As + b * 2560;
        const uint32_t* Bb = Bs + b * 2560;
#pragma unroll
        for (int th = 0; th < 2; th++) {
            int kc = th * 8 + c4;
            uint32_t af[4][4], bf[4][2];
#pragma unroll
            for (int mt = 0; mt < 4; mt++) {
                const uint32_t* ap = Ab + (wm + mt * 16 + g) * 20 + kc;
                af[mt][0] = ap[0]; af[mt][1] = ap[160]; af[mt][2] = ap[4]; af[mt][3] = ap[164];
            }
#pragma unroll
            for (int nt = 0; nt < 4; nt++) {
                const uint32_t* bp = Bb + (wn + nt * 8 + g) * 20 + kc;
                bf[nt][0] = bp[0]; bf[nt][1] = bp[4];
            }
#pragma unroll
            for (int mt = 0; mt < 4; mt++)
#pragma unroll
                for (int nt = 0; nt < 4; nt++) mma8(acc[mt][nt], af[mt], bf[nt]);
        }
    }
    float* dst = g_t7p + (size_t)(n * NSPLIT + s) * K3 * CC;
#pragma unroll
    for (int mt = 0; mt < 4; mt++)
#pragma unroll
        for (int nt = 0; nt < 4; nt++) {
            int row = m0 + wm + mt * 16 + g;
            int col = c0 + wn + nt * 8 + c4 * 2;
            *reinterpret_cast<float2*>(&dst[(size_t)row * CC + col]) =
                make_float2(acc[mt][nt][0], acc[mt][nt][1]);
            *reinterpret_cast<float2*>(&dst[(size_t)(row + 8) * CC + col]) =
                make_float2(acc[mt][nt][2], acc[mt][nt][3]);
        }
}

// ---------------- Stage 3: out = (t6^T @ t7) / sqrt(768) ----------------
__global__ __launch_bounds__(256, 2) void k3(float* __restrict__ out) {
    __shared__ uint32_t As[3 * 2048];
    __shared__ uint32_t Bs[3 * 2048];
    const int t = threadIdx.x, lane = t & 31, warp = t >> 5;
    const int n = blockIdx.z, mb = blockIdx.y, m0 = mb * 128;
    const int p0 = blockIdx.x * 128, pt0 = blockIdx.x * 16;
    const int g = lane >> 2, c4 = lane & 3;
    const int wm = (warp & 1) * 64, wn = (warp >> 1) * 32;

    const uint32_t* srcA = g_t7f + ((size_t)n * 49152 + (size_t)mb * 96 * 256 + t) * 4;
    const uint32_t* srcB = g_t6f + (((size_t)n * 96 * 392 + pt0) * 32) * 2 + t * 4;
    const uint32_t dA = cvta_s(As) + t * 16;
    const uint32_t dB = cvta_s(Bs) + t * 16;

    auto load = [&](int kb, int buf) {
        CPA(dA + buf * 8192,        srcA + kb * 2048);
        CPA(dA + buf * 8192 + 4096, srcA + kb * 2048 + 1024);
        CPA(dB + buf * 8192,        srcB + (size_t)kb * 50176);
        CPA(dB + buf * 8192 + 4096, srcB + (size_t)kb * 50176 + 25088);
    };

    ACC_INIT
    load(0, 0); CPC(); load(1, 1); CPC();
    const int NK = 48;
    for (int kb = 0; kb < NK; kb++) {
        int b = kb % 3;
        CPW(1); __syncthreads();
        if (kb + 2 < NK) load(kb + 2, (kb + 2) % 3);
        CPC();
        const uint32_t* Ab = As + b * 2048;
        const uint32_t* Bb = Bs + b * 2048;
#pragma unroll
        for (int th = 0; th < 2; th++) {
            uint4 af[4]; uint2 bf[4];
#pragma unroll
            for (int mt = 0; mt < 4; mt++)
                af[mt] = *reinterpret_cast<const uint4*>(
                    Ab + ((th * 8 + (warp & 1) * 4 + mt) * 32 + lane) * 4);
#pragma unroll
            for (int nt = 0; nt < 4; nt++)
                bf[nt] = *reinterpret_cast<const uint2*>(
                    Bb + ((th * 16 + (warp >> 1) * 4 + nt) * 32 + lane) * 2);
#pragma unroll
            for (int mt = 0; mt < 4; mt++)
#pragma unroll
                for (int nt = 0; nt < 4; nt++)
                    mma8(acc[mt][nt], reinterpret_cast<const uint32_t*>(&af[mt]),
                                      reinterpret_cast<const uint32_t*>(&bf[nt]));
        }
    }
#pragma unroll
    for (int mt = 0; mt < 4; mt++)
#pragma unroll
        for (int nt = 0; nt < 4; nt++) {
            int row = m0 + wm + mt * 16 + g;
            int col = p0 + wn + nt * 8 + c4 * 2;
            if (col < HWL) {
                float* o0 = out + ((size_t)n * CC + row) * HWL + col;
                float* o1 = out + ((size_t)n * CC + row + 8) * HWL + col;
                *reinterpret_cast<float2*>(o0) =
                    make_float2(acc[mt][nt][0] * RS768, acc[mt][nt][1] * RS768);
                *reinterpret_cast<float2*>(o1) =
                    make_float2(acc[mt][nt][2] * RS768, acc[mt][nt][3] * RS768);
            }
        }
}

extern "C" void kernel_launch(void* const* d_in, const int* in_sizes, int n_in,
                              void* d_out, int out_size) {
    const float* x   = (const float*)d_in[0];   // (16, 256, 56, 56)
    const float* W3  = (const float*)d_in[1];   // (256, 768)
    const float* p7w = (const float*)d_in[2];   // (1, 256, 3, 256)
    float* out = (float*)d_out;                 // (16, 256, 56, 56)

    // null: p_cvtw -> p_t1_a [e1a] -> p_t1_b [e1b] -> k1 -> p_t6
    //       -> (wait e2) -> k3
    // s2:   (wait e1a) -> k2_a -> (wait e1b) -> k2_b -> k2r [e2]
    p_cvtw<<<192, 256>>>(W3);
    p_t1  <<<18816, 256>>>(x, 0);
    cudaEventRecord(g_e1a, 0);
    p_t1  <<<18816, 256>>>(x, 8);
    cudaEventRecord(g_e1b, 0);

    cudaStreamWaitEvent(g_s2, g_e1a, 0);
    k2    <<<dim3(2, 6, 24), 256, 0, g_s2>>>(0);
    cudaStreamWaitEvent(g_s2, g_e1b, 0);
    k2    <<<dim3(2, 6, 24), 256, 0, g_s2>>>(8);
    k2r   <<<3072, 256, 0, g_s2>>>(p7w);
    cudaEventRecord(g_e2, g_s2);

    k1    <<<dim3(25, 2, 16), 256>>>();
    p_t6  <<<75264, 256>>>(x);

    cudaStreamWaitEvent(0, g_e2, 0);
    k3    <<<dim3(25, 2, 16), 256>>>(out);
}

// round 17
// speedup vs baseline: 1.0238x; 1.0052x over previous
#include <cuda_runtime.h>
#include <cstdint>
#include <math.h>

#define CC   256
#define K3   768
#define HWL  3136
#define WD   56
#define HALF_PI 1.5707963f
#define INV56   (1.0f / 56.0f)
#define RS768   0.03608439182435161f   // 1/sqrt(768)
#define NSPLIT  3

// Scratch (device globals — no allocations allowed).
__device__ uint32_t g_w3f [2 * 96 * 8 * 32 * 4];          // tf32(W3), A-frag
__device__ uint32_t g_t1tf[16 * K3 * HWL + 128];          // tf32(unfold(x)) row-major
__device__ float    g_t3  [16 * CC * HWL];                // fp32 t3
__device__ uint32_t g_t6f [16 * 96 * 392 * 32 * 2 + 1024];// tf32(max(t3,sin)), B-frag
__device__ float    g_t7p [16 * NSPLIT * K3 * CC];        // split-K partials
__device__ uint32_t g_t7f [16 * 2 * 96 * 8 * 32 * 4];     // tf32(t7), A-frag

// Host-side stream/event objects (host resources only, created at load).
static cudaStream_t g_s2;
static cudaEvent_t  g_e1a, g_e1b, g_e2;
namespace {
struct StreamInit {
    StreamInit() {
        cudaStreamCreateWithFlags(&g_s2, cudaStreamNonBlocking);
        cudaEventCreateWithFlags(&g_e1a, cudaEventDisableTiming);
        cudaEventCreateWithFlags(&g_e1b, cudaEventDisableTiming);
        cudaEventCreateWithFlags(&g_e2,  cudaEventDisableTiming);
    }
} g_stream_init;
}

static __device__ __forceinline__ uint32_t f2tf(float f) {
    uint32_t u; asm("cvt.rna.tf32.f32 %0, %1;" : "=r"(u) : "f"(f)); return u;
}
static __device__ __forceinline__ uint32_t cvta_s(const void* p) {
    uint32_t a;
    asm("{ .reg .u64 t; cvta.to.shared.u64 t, %1; cvt.u32.u64 %0, t; }" : "=r"(a) : "l"(p));
    return a;
}
static __device__ __forceinline__ void mma8(float d[4], const uint32_t* a, const uint32_t* b) {
    asm volatile(
        "mma.sync.aligned.m16n8k8.row.col.f32.tf32.tf32.f32 "
        "{%0,%1,%2,%3},{%4,%5,%6,%7},{%8,%9},{%0,%1,%2,%3};"
        : "+f"(d[0]), "+f"(d[1]), "+f"(d[2]), "+f"(d[3])
        : "r"(a[0]), "r"(a[1]), "r"(a[2]), "r"(a[3]), "r"(b[0]), "r"(b[1]));
}
#define CPA(dst, src) asm volatile("cp.async.cg.shared.global [%0], [%1], 16;" :: "r"(dst), "l"(src) : "memory")
#define CPC()         asm volatile("cp.async.commit_group;" ::: "memory")
#define CPW(N)        asm volatile("cp.async.wait_group %0;" :: "n"(N) : "memory")

// =====================================================================
// Precompute kernels
// =====================================================================
__global__ __launch_bounds__(256) void p_cvtw(const float* __restrict__ w) {
    int id = blockIdx.x * 256 + threadIdx.x;
    int l = id & 31, g = l >> 2, c4 = l & 3;
    int mt = (id >> 5) & 7;
    int r = id >> 8;
    int kt = r % 96, mb = r / 96;
    int m = mb * 128 + mt * 16 + g;
    int k = kt * 8 + c4;
    uint4 o;
    o.x = f2tf(w[(size_t)m * K3 + k]);
    o.y = f2tf(w[(size_t)(m + 8) * K3 + k]);
    o.z = f2tf(w[(size_t)m * K3 + k + 4]);
    o.w = f2tf(w[(size_t)(m + 8) * K3 + k + 4]);
    reinterpret_cast<uint4*>(g_w3f)[id] = o;
}
// t1 row-major; n0 = batch offset (covers 8 batches per launch)
__global__ __launch_bounds__(256) void p_t1(const float* __restrict__ x, int n0) {
    int idx = blockIdx.x * 256 + threadIdx.x;
    int p4 = idx % (HWL / 4);
    int r  = idx / (HWL / 4);
    int k  = r % K3;
    int n  = n0 + r / K3;
    int c = k / 3, tap = k - 3 * c, sh = 2 * tap - 2;
    int p = p4 * 4, w = p % WD;
    const float* xr = x + ((size_t)n * CC + c) * HWL + p + sh;
    float v[4];
#pragma unroll
    for (int j = 0; j < 4; j++)
        v[j] = ((unsigned)(w + j + sh) < WD) ? xr[j] : 0.f;
    reinterpret_cast<uint4*>(g_t1tf)[(size_t)n * (K3 * HWL / 4) + (size_t)k * (HWL / 4) + p4] =
        make_uint4(f2tf(v[0]), f2tf(v[1]), f2tf(v[2]), f2tf(v[3]));
}
// t6 -> B-frag pairs via smem staging
__global__ __launch_bounds__(256) void p_t6(const float* __restrict__ x) {
    __shared__ float S[8 * 72];
    const int t = threadIdx.x;
    int bid = blockIdx.x;
    int ptg = bid % 49; bid /= 49;
    int kq  = bid % 96; int n = bid / 96;
    const int p0 = ptg * 64;
#pragma unroll
    for (int q = 0; q < 2; q++) {
        int item = t + q * 256;
        int k8 = item >> 6, pi = item & 63;
        int k = kq * 8 + k8;
        int c = k / 3, tap = k - 3 * c, sh = 2 * tap - 2;
        int p = p0 + pi, w = p % WD;
        const float* base = x + ((size_t)n * CC + c) * HWL + p;
        float s = ((unsigned)(w + sh) < WD) ? __sinf(HALF_PI * base[sh]) : 0.f;
        float v = fmaxf(g_t3[((size_t)n * CC + c) * HWL + p], s);
        S[k8 * 72 + pi] = v;
    }
    __syncthreads();
    int ptl = t >> 5, l = t & 31;
    int g = l >> 2, c4 = l & 3;
    int pl = ptl * 8 + g;
    uint2 o;
    o.x = f2tf(S[c4 * 72 + pl]);
    o.y = f2tf(S[(c4 + 4) * 72 + pl]);
    reinterpret_cast<uint2*>(g_t6f)[(((size_t)n * 96 + kq) * 392 + ptg * 8 + ptl) * 32 + l] = o;
}
// reduce split-K partials, * INV56 * p7w -> t7 in A-frag chunks
__global__ __launch_bounds__(256) void k2r(const float* __restrict__ p7w) {
    int id = blockIdx.x * 256 + threadIdx.x;
    int l = id & 31, g = l >> 2, c4 = l & 3;
    int mt = (id >> 5) & 7;
    int r = id >> 8;
    int kt = r % 96; r /= 96;
    int mb = r & 1;  int n = r >> 1;
    const float* P = g_t7p + (size_t)n * NSPLIT * (K3 * CC);
    uint32_t vals[4];
#pragma unroll
    for (int q = 0; q < 4; q++) {
        int dk = (q >> 1) * 4, dm = (q & 1) * 8;
        int k = kt * 8 + c4 + dk;
        int m = mb * 128 + mt * 16 + g + dm;
        int off = k * CC + m;
        float sum = P[off] + P[K3 * CC + off] + P[2 * K3 * CC + off];
        vals[q] = f2tf(sum * INV56 * p7w[off]);
    }
    reinterpret_cast<uint4*>(g_t7f)[id] = make_uint4(vals[0], vals[1], vals[2], vals[3]);
}

#define ACC_INIT float acc[4][4][4]; \
    _Pragma("unroll") for (int i0 = 0; i0 < 4; i0++) \
    _Pragma("unroll") for (int j0 = 0; j0 < 4; j0++) \
    _Pragma("unroll") for (int r0 = 0; r0 < 4; r0++) acc[i0][j0][r0] = 0.f;

// ---------------- Stage 1: t3 = W3 @ t1 (4-stage pipeline) ----------------
__global__ __launch_bounds__(256, 2) void k1() {
    __shared__ uint32_t As[4 * 2048];
    __shared__ uint32_t Bs[4 * 2176];
    const int t = threadIdx.x, lane = t & 31, warp = t >> 5;
    const int n = blockIdx.z, mb = blockIdx.y, m0 = mb * 128, p0 = blockIdx.x * 128;
    const int g = lane >> 2, c4 = lane & 3;
    const int wm = (warp & 1) * 64, wn = (warp >> 1) * 32;
    const uint32_t* t1n = g_t1tf + (size_t)n * K3 * HWL;

    const uint32_t* srcA = g_w3f + ((size_t)mb * 96 * 256 + t) * 4;
    const int rB0 = t >> 5, sB0 = t & 31;
    const uint32_t* srcB0 = t1n + (size_t)rB0 * HWL + p0 + sB0 * 4;
    const uint32_t* srcB1 = t1n + (size_t)(rB0 + 8) * HWL + p0 + sB0 * 4;
    const uint32_t dA  = cvta_s(As) + t * 16;
    const uint32_t dB0 = cvta_s(&Bs[rB0 * 136 + sB0 * 4]);
    const uint32_t dB1 = cvta_s(&Bs[(rB0 + 8) * 136 + sB0 * 4]);

    auto load = [&](int kb, int buf) {
        int k0 = kb * 16;
        CPA(dA + buf * 8192,        srcA + kb * 2048);
        CPA(dA + buf * 8192 + 4096, srcA + kb * 2048 + 1024);
        CPA(dB0 + buf * 8704, srcB0 + (size_t)k0 * HWL);
        CPA(dB1 + buf * 8704, srcB1 + (size_t)k0 * HWL);
    };

    ACC_INIT
    load(0, 0); CPC(); load(1, 1); CPC(); load(2, 2); CPC();
    const int NK = 48;
    for (int kb = 0; kb < NK; kb++) {
        int b = kb & 3;
        CPW(2); __syncthreads();
        if (kb + 3 < NK) load(kb + 3, (kb + 3) & 3);
        CPC();
        const uint32_t* Ab = As + b * 2048;
        const uint32_t* Bb = Bs + b * 2176;
#pragma unroll
        for (int th = 0; th < 2; th++) {
            int kc = th * 8 + c4;
            uint4 af[4]; uint32_t bf[4][2];
#pragma unroll
            for (int mt = 0; mt < 4; mt++)
                af[mt] = *reinterpret_cast<const uint4*>(
                    Ab + ((th * 8 + (warp & 1) * 4 + mt) * 32 + lane) * 4);
#pragma unroll
            for (int nt = 0; nt < 4; nt++) {
                const uint32_t* bp = Bb + kc * 136 + wn + nt * 8 + g;
                bf[nt][0] = bp[0]; bf[nt][1] = bp[544];
            }
#pragma unroll
            for (int mt = 0; mt < 4; mt++)
#pragma unroll
                for (int nt = 0; nt < 4; nt++)
                    mma8(acc[mt][nt], reinterpret_cast<const uint32_t*>(&af[mt]), bf[nt]);
        }
    }
    float* t3n = g_t3 + (size_t)n * CC * HWL;
#pragma unroll
    for (int mt = 0; mt < 4; mt++)
#pragma unroll
        for (int nt = 0; nt < 4; nt++) {
            int row = m0 + wm + mt * 16 + g;
            int col = p0 + wn + nt * 8 + c4 * 2;
            if (col < HWL) {
                *reinterpret_cast<float2*>(&t3n[(size_t)row * HWL + col]) =
                    make_float2(acc[mt][nt][0], acc[mt][nt][1]);
                *reinterpret_cast<float2*>(&t3n[(size_t)(row + 8) * HWL + col]) =
                    make_float2(acc[mt][nt][2], acc[mt][nt][3]);
            }
        }
}

// ---------------- Stage 2: t7p = t2 @ x^T (split-K=3, 4-stage); n0 = batch offset ----------------
__global__ __launch_bounds__(256, 2) void k2(int n0) {
    __shared__ uint32_t As[4 * 2560];
    __shared__ uint32_t Bs[4 * 2560];
    const int t = threadIdx.x, lane = t & 31, warp = t >> 5;
    const int zz = blockIdx.z, n = n0 + zz / NSPLIT, s = zz % NSPLIT;
    const int m0 = blockIdx.y * 128, c0 = blockIdx.x * 128;
    const int pbase = s * 1056;
    const int NK = (s == 2) ? 64 : 66;
    const int g = lane >> 2, c4 = lane & 3;
    const int wm = (warp & 1) * 64, wn = (warp >> 1) * 32;
    const uint32_t* t1n = g_t1tf + (size_t)n * K3 * HWL;

    const int rA = t >> 2, sA = t & 3;
    int mk0 = m0 + rA, mk1 = m0 + rA + 64;
    int sk0 = (mk0 >= 3) ? mk0 - 3 : mk0 + 765;
    int sk1 = (mk1 >= 3) ? mk1 - 3 : mk1 + 765;
    const uint32_t* srcA0 = t1n + (size_t)sk0 * HWL + pbase + sA * 4;
    const uint32_t* srcA1 = t1n + (size_t)sk1 * HWL + pbase + sA * 4;
    const uint32_t* srcB0 = t1n + (size_t)(3 * (c0 + rA) + 1) * HWL + pbase + sA * 4;
    const uint32_t* srcB1 = t1n + (size_t)(3 * (c0 + rA + 64) + 1) * HWL + pbase + sA * 4;
    const uint32_t dA0 = cvta_s(&As[rA * 20 + sA * 4]);
    const uint32_t dA1 = cvta_s(&As[(rA + 64) * 20 + sA * 4]);
    const uint32_t dB0 = cvta_s(&Bs[rA * 20 + sA * 4]);
    const uint32_t dB1 = cvta_s(&Bs[(rA + 64) * 20 + sA * 4]);

    auto load = [&](int kb, int buf) {
        int o = kb * 16;
        CPA(dA0 + buf * 10240, srcA0 + o);
        CPA(dA1 + buf * 10240, srcA1 + o);
        CPA(dB0 + buf * 10240, srcB0 + o);
        CPA(dB1 + buf * 10240, srcB1 + o);
    };

    ACC_INIT
    load(0, 0); CPC(); load(1, 1); CPC(); load(2, 2); CPC();
    for (int kb = 0; kb < NK; kb++) {
        int b = kb & 3;
        CPW(2); __syncthreads();
        if (kb + 3 < NK) load(kb + 3, (kb + 3) & 3);
        CPC();
        const uint32_t* Ab = As + b * 2560;
        const uint32_t* Bb = Bs + b * 2560;
#pragma unroll
        for (int th = 0; th < 2; th++) {
            int kc = th * 8 + c4;
            uint32_t af[4][4], bf[4][2];
#pragma unroll
            for (int mt = 0; mt < 4; mt++) {
                const uint32_t* ap = Ab + (wm + mt * 16 + g) * 20 + kc;
                af[mt][0] = ap[0]; af[mt][1] = ap[160]; af[mt][2] = ap[4]; af[mt][3] = ap[164];
            }
#pragma unroll
            for (int nt = 0; nt < 4; nt++) {
                const uint32_t* bp = Bb + (wn + nt * 8 + g) * 20 + kc;
                bf[nt][0] = bp[0]; bf[nt][1] = bp[4];
            }
#pragma unroll
            for (int mt = 0; mt < 4; mt++)
#pragma unroll
                for (int nt = 0; nt < 4; nt++) mma8(acc[mt][nt], af[mt], bf[nt]);
        }
    }
    float* dst = g_t7p + (size_t)(n * NSPLIT + s) * K3 * CC;
#pragma unroll
    for (int mt = 0; mt < 4; mt++)
#pragma unroll
        for (int nt = 0; nt < 4; nt++) {
            int row = m0 + wm + mt * 16 + g;
            int col = c0 + wn + nt * 8 + c4 * 2;
            *reinterpret_cast<float2*>(&dst[(size_t)row * CC + col]) =
                make_float2(acc[mt][nt][0], acc[mt][nt][1]);
            *reinterpret_cast<float2*>(&dst[(size_t)(row + 8) * CC + col]) =
                make_float2(acc[mt][nt][2], acc[mt][nt][3]);
        }
}

// ---------------- Stage 3: out = (t6^T @ t7) / sqrt(768) (4-stage) ----------------
__global__ __launch_bounds__(256, 2) void k3(float* __restrict__ out) {
    __shared__ uint32_t As[4 * 2048];
    __shared__ uint32_t Bs[4 * 2048];
    const int t = threadIdx.x, lane = t & 31, warp = t >> 5;
    const int n = blockIdx.z, mb = blockIdx.y, m0 = mb * 128;
    const int p0 = blockIdx.x * 128, pt0 = blockIdx.x * 16;
    const int g = lane >> 2, c4 = lane & 3;
    const int wm = (warp & 1) * 64, wn = (warp >> 1) * 32;

    const uint32_t* srcA = g_t7f + ((size_t)n * 49152 + (size_t)mb * 96 * 256 + t) * 4;
    const uint32_t* srcB = g_t6f + (((size_t)n * 96 * 392 + pt0) * 32) * 2 + t * 4;
    const uint32_t dA = cvta_s(As) + t * 16;
    const uint32_t dB = cvta_s(Bs) + t * 16;

    auto load = [&](int kb, int buf) {
        CPA(dA + buf * 8192,        srcA + kb * 2048);
        CPA(dA + buf * 8192 + 4096, srcA + kb * 2048 + 1024);
        CPA(dB + buf * 8192,        srcB + (size_t)kb * 50176);
        CPA(dB + buf * 8192 + 4096, srcB + (size_t)kb * 50176 + 25088);
    };

    ACC_INIT
    load(0, 0); CPC(); load(1, 1); CPC(); load(2, 2); CPC();
    const int NK = 48;
    for (int kb = 0; kb < NK; kb++) {
        int b = kb & 3;
        CPW(2); __syncthreads();
        if (kb + 3 < NK) load(kb + 3, (kb + 3) & 3);
        CPC();
        const uint32_t* Ab = As + b * 2048;
        const uint32_t* Bb = Bs + b * 2048;
#pragma unroll
        for (int th = 0; th < 2; th++) {
            uint4 af[4]; uint2 bf[4];
#pragma unroll
            for (int mt = 0; mt < 4; mt++)
                af[mt] = *reinterpret_cast<const uint4*>(
                    Ab + ((th * 8 + (warp & 1) * 4 + mt) * 32 + lane) * 4);
#pragma unroll
            for (int nt = 0; nt < 4; nt++)
                bf[nt] = *reinterpret_cast<const uint2*>(
                    Bb + ((th * 16 + (warp >> 1) * 4 + nt) * 32 + lane) * 2);
#pragma unroll
            for (int mt = 0; mt < 4; mt++)
#pragma unroll
                for (int nt = 0; nt < 4; nt++)
                    mma8(acc[mt][nt], reinterpret_cast<const uint32_t*>(&af[mt]),
                                      reinterpret_cast<const uint32_t*>(&bf[nt]));
        }
    }
#pragma unroll
    for (int mt = 0; mt < 4; mt++)
#pragma unroll
        for (int nt = 0; nt < 4; nt++) {
            int row = m0 + wm + mt * 16 + g;
            int col = p0 + wn + nt * 8 + c4 * 2;
            if (col < HWL) {
                float* o0 = out + ((size_t)n * CC + row) * HWL + col;
                float* o1 = out + ((size_t)n * CC + row + 8) * HWL + col;
                *reinterpret_cast<float2*>(o0) =
                    make_float2(acc[mt][nt][0] * RS768, acc[mt][nt][1] * RS768);
                *reinterpret_cast<float2*>(o1) =
                    make_float2(acc[mt][nt][2] * RS768, acc[mt][nt][3] * RS768);
            }
        }
}

extern "C" void kernel_launch(void* const* d_in, const int* in_sizes, int n_in,
                              void* d_out, int out_size) {
    const float* x   = (const float*)d_in[0];   // (16, 256, 56, 56)
    const float* W3  = (const float*)d_in[1];   // (256, 768)
    const float* p7w = (const float*)d_in[2];   // (1, 256, 3, 256)
    float* out = (float*)d_out;                 // (16, 256, 56, 56)

    // null: p_cvtw -> p_t1_a [e1a] -> p_t1_b [e1b] -> k1 -> p_t6
    //       -> (wait e2) -> k3
    // s2:   (wait e1a) -> k2_a -> (wait e1b) -> k2_b -> k2r [e2]
    p_cvtw<<<192, 256>>>(W3);
    p_t1  <<<18816, 256>>>(x, 0);
    cudaEventRecord(g_e1a, 0);
    p_t1  <<<18816, 256>>>(x, 8);
    cudaEventRecord(g_e1b, 0);

    cudaStreamWaitEvent(g_s2, g_e1a, 0);
    k2    <<<dim3(2, 6, 24), 256, 0, g_s2>>>(0);
    cudaStreamWaitEvent(g_s2, g_e1b, 0);
    k2    <<<dim3(2, 6, 24), 256, 0, g_s2>>>(8);
    k2r   <<<3072, 256, 0, g_s2>>>(p7w);
    cudaEventRecord(g_e2, g_s2);

    k1    <<<dim3(25, 2, 16), 256>>>();
    p_t6  <<<75264, 256>>>(x);

    cudaStreamWaitEvent(0, g_e2, 0);
    k3    <<<dim3(25, 2, 16), 256>>>(out);
}